// round 17
// baseline (speedup 1.0000x reference)
#include <cuda_runtime.h>
#include <cuda_fp16.h>

#define B_  16
#define S_  2048
#define D_  128
#define BQ  128
#define BK  64
#define NT  256
#define NTILES (S_/BK)

#define STR 272              // smem row stride in bytes (128 f16 + 8 pad)

#define OFF_Q   0            // 128 x 272 = 34816
#define OFF_K0  34816        // 64 x 272  = 17408
#define OFF_K1  52224
#define OFF_V0  69632
#define OFF_V1  87040
#define OFF_KPM 104448       // 2 x 64B slots
#define SMEM_BYTES (104576 + 128)

// f16 scratch (written by cvt prepass, read by main kernel)
__device__ __half g_Qh[B_*S_*D_];
__device__ __half g_Kh[B_*S_*D_];
__device__ __half g_Vh[B_*S_*D_];

__device__ __forceinline__ unsigned smem_u32(const void* p) {
    unsigned a;
    asm("{ .reg .u64 t; cvta.to.shared.u64 t, %1; cvt.u32.u64 %0, t; }" : "=r"(a) : "l"(p));
    return a;
}

#define LDSM_X4(r0,r1,r2,r3,a) \
    asm("ldmatrix.sync.aligned.m8n8.x4.shared.b16 {%0,%1,%2,%3}, [%4];" \
        : "=r"(r0),"=r"(r1),"=r"(r2),"=r"(r3) : "r"(a) : "memory")
#define LDSM_X4T(r0,r1,r2,r3,a) \
    asm("ldmatrix.sync.aligned.m8n8.x4.trans.shared.b16 {%0,%1,%2,%3}, [%4];" \
        : "=r"(r0),"=r"(r1),"=r"(r2),"=r"(r3) : "r"(a) : "memory")

#define MMA(c,a0,a1,a2,a3,b0,b1) \
    asm("mma.sync.aligned.m16n8k16.row.col.f32.f16.f16.f32 " \
        "{%0,%1,%2,%3}, {%4,%5,%6,%7}, {%8,%9}, {%0,%1,%2,%3};" \
        : "+f"((c)[0]),"+f"((c)[1]),"+f"((c)[2]),"+f"((c)[3]) \
        : "r"(a0),"r"(a1),"r"(a2),"r"(a3),"r"(b0),"r"(b1))

#define CPA16(dst, src) \
    asm volatile("cp.async.cg.shared.global [%0], [%1], 16;" :: "r"(dst), "l"(src))
#define CPA4(dst, src) \
    asm volatile("cp.async.ca.shared.global [%0], [%1], 4;" :: "r"(dst), "l"(src))
#define CP_COMMIT()  asm volatile("cp.async.commit_group;")
#define CP_WAIT(n)   asm volatile("cp.async.wait_group %0;" :: "n"(n) : "memory")

__device__ __forceinline__ unsigned pack2h(float x, float y) {
    __half2 h = __floats2half2_rn(x, y);   // x -> low half
    return *reinterpret_cast<unsigned*>(&h);
}

// ---- prepass: f32 -> f16 conversion (Q pre-scaled) ----
__global__ __launch_bounds__(256, 8)
void cvt_kernel(const float* __restrict__ Q, const float* __restrict__ K,
                const float* __restrict__ V)
{
    const int t = blockIdx.x * 256 + threadIdx.x;   // one float4 per thread
    const float* src;
    __half* dst;
    float mul = 1.0f;
    if (blockIdx.y == 0)      { src = Q; dst = g_Qh; mul = 0.08838834764831845f; }
    else if (blockIdx.y == 1) { src = K; dst = g_Kh; }
    else                      { src = V; dst = g_Vh; }
    float4 v = reinterpret_cast<const float4*>(src)[t];
    unsigned h0 = pack2h(v.x * mul, v.y * mul);
    unsigned h1 = pack2h(v.z * mul, v.w * mul);
    reinterpret_cast<uint2*>(dst)[t] = make_uint2(h0, h1);
}

// prefetch f16 K/V tile + kpm into smem buffers via cp.async (one group)
__device__ __forceinline__ void prefetch_kv(unsigned sb, const __half* kh, const __half* vh,
                                            const unsigned char* kpmg, unsigned offK,
                                            unsigned offV, int slot, int tid)
{
    const char* gk = (const char*)kh;
    const char* gv = (const char*)vh;
    #pragma unroll
    for (int it = 0; it < 4; ++it) {
        int idx = tid + it * NT;              // 16B chunk over [64 rows][16 chunks]
        unsigned r = (unsigned)(idx >> 4), c = (unsigned)(idx & 15);
        CPA16(sb + offK + r * STR + c * 16, gk + idx * 16);
        CPA16(sb + offV + r * STR + c * 16, gv + idx * 16);
    }
    if (tid < 16) CPA4(sb + OFF_KPM + (unsigned)(slot * 64 + tid * 4), kpmg + tid * 4);
    CP_COMMIT();
}

__global__ __launch_bounds__(NT, 1)
void fa_f16_kernel(const unsigned char* __restrict__ kpm,
                   const int* __restrict__ cls, float* __restrict__ O)
{
    extern __shared__ char smc[];
    const unsigned sb = smem_u32(smc);
    const int tid  = threadIdx.x;
    const int wid  = tid >> 5;
    const int lane = tid & 31;
    const int b  = blockIdx.y;
    const int q0 = blockIdx.x * BQ;

    const int i0 = cls[b*3 + 0];
    const int i1 = cls[b*3 + 1];
    const int i2 = cls[b*3 + 2];

    const int rg0 = q0 + wid*16 + (lane >> 2);
    const int rg1 = rg0 + 8;
    const bool isr1_0 = (rg0 == i1), isr2_0 = (rg0 == i2);
    const bool isr1_1 = (rg1 == i1), isr2_1 = (rg1 == i2);
    const bool special = isr1_0 || isr2_0 || isr1_1 || isr2_1;

    // prologue: prefetch tile 0 K/V (f16) into buffer 0
    prefetch_kv(sb, g_Kh + (size_t)b*S_*D_, g_Vh + (size_t)b*S_*D_,
                kpm + (size_t)b*S_, OFF_K0, OFF_V0, 0, tid);

    // Q tile (already scaled f16) -> smem
    {
        const uint4* qg = reinterpret_cast<const uint4*>(g_Qh + ((size_t)b*S_ + q0)*D_);
        #pragma unroll
        for (int it = 0; it < 8; ++it) {
            int idx = tid + it * NT;          // 16B chunk over [128 rows][16 chunks]
            unsigned r = (unsigned)(idx >> 4), c = (unsigned)(idx & 15);
            *reinterpret_cast<uint4*>(smc + OFF_Q + r * STR + c * 16) = qg[idx];
        }
    }

    // ldmatrix lane addressing
    const unsigned qrow_off = (unsigned)((wid*16 + (lane & 15)) * STR) + ((lane >> 4) ? 16u : 0u);
    const unsigned krow     = (unsigned)((((lane >> 4) & 1) * 8 + (lane & 7)) * STR) + (((lane >> 3) & 1) ? 16u : 0u);
    const unsigned vrow     = (unsigned)(((((lane >> 3) & 1) * 8) + (lane & 7)) * STR) + ((lane >> 4) ? 16u : 0u);

    __syncthreads();          // Q smem complete
    unsigned aq[8][4];
    #pragma unroll
    for (int ks = 0; ks < 8; ++ks)
        LDSM_X4(aq[ks][0], aq[ks][1], aq[ks][2], aq[ks][3],
                sb + OFF_Q + qrow_off + (unsigned)(ks * 32));

    float o[16][4];
    #pragma unroll
    for (int i = 0; i < 16; ++i)
        #pragma unroll
        for (int j = 0; j < 4; ++j) o[i][j] = 0.0f;
    float lsum0 = 0.0f, lsum1 = 0.0f;

    const int m_ = lane & 3;

    for (int tl = 0; tl < NTILES; ++tl) {
        const int kb = tl * BK;
        const int p  = tl & 1;
        const unsigned offK = p ? OFF_K1 : OFF_K0;
        const unsigned offV = p ? OFF_V1 : OFF_V0;

        // issue next tile's prefetch into the other buffer, then wait for this tile
        if (tl + 1 < NTILES) {
            prefetch_kv(sb, g_Kh + ((size_t)b*S_ + kb + BK)*D_,
                        g_Vh + ((size_t)b*S_ + kb + BK)*D_,
                        kpm + (size_t)b*S_ + kb + BK,
                        p ? OFF_K0 : OFF_K1, p ? OFF_V0 : OFF_V1, 1 - p, tid);
            CP_WAIT(1);
        } else {
            CP_WAIT(0);
        }
        __syncthreads();      // this tile's copies visible to all warps

        const unsigned short* kpmh = (const unsigned short*)(smc + OFF_KPM + p*64);

        // ---- fused per-16-key-group: QK -> mask -> exp -> PV ----
        #pragma unroll
        for (int np = 0; np < 4; ++np) {
            // QK for n-tiles 2np, 2np+1 (keys np*16 .. np*16+15)
            float s0[4], s1[4];
            #pragma unroll
            for (int j = 0; j < 4; ++j) { s0[j] = 0.0f; s1[j] = 0.0f; }
            #pragma unroll
            for (int ks = 0; ks < 8; ++ks) {
                unsigned roff = (unsigned)(np * 16 * STR) + krow + (unsigned)(ks * 32);
                unsigned b0, b1, b2, b3;
                LDSM_X4(b0, b1, b2, b3, sb + offK + roff);
                MMA(s0, aq[ks][0], aq[ks][1], aq[ks][2], aq[ks][3], b0, b1);
                MMA(s1, aq[ks][0], aq[ks][1], aq[ks][2], aq[ks][3], b2, b3);
            }

            // mask (fast path for non-special threads)
            {
                unsigned kpw0 = kpmh[(2*np)*4 + m_];
                unsigned kpw1 = kpmh[(2*np+1)*4 + m_];
                if (!special) {
                    if (kpw0 & 0xFFu) { s0[0] = -1e30f; s0[2] = -1e30f; }
                    if (kpw0 >> 8)    { s0[1] = -1e30f; s0[3] = -1e30f; }
                    if (kpw1 & 0xFFu) { s1[0] = -1e30f; s1[2] = -1e30f; }
                    if (kpw1 >> 8)    { s1[1] = -1e30f; s1[3] = -1e30f; }
                } else {
                    #pragma unroll
                    for (int h = 0; h < 2; ++h) {
                        float* sx = h ? s1 : s0;
                        unsigned kpw = h ? kpw1 : kpw0;
                        const int jl0 = (2*np + h)*8 + m_*2;
                        const int jg0 = kb + jl0, jg1 = jg0 + 1;
                        const bool kp0 = (kpw & 0xFFu) != 0, kp1 = (kpw >> 8) != 0;
                        const bool key1_0 = ((jg0 > i1) && (jg0 <= i2)) || (jg0 == 0);
                        const bool key1_1 = ((jg1 > i1) && (jg1 <= i2)) || (jg1 == 0);
                        const bool key2_0 = ((jg0 > i0) && (jg0 <= i1)) || (jg0 == 0);
                        const bool key2_1 = ((jg1 > i0) && (jg1 <= i1)) || (jg1 == 0);
                        if (kp0 || (isr1_0 && key1_0) || (isr2_0 && key2_0)) sx[0] = -1e30f;
                        if (kp1 || (isr1_0 && key1_1) || (isr2_0 && key2_1)) sx[1] = -1e30f;
                        if (kp0 || (isr1_1 && key1_0) || (isr2_1 && key2_0)) sx[2] = -1e30f;
                        if (kp1 || (isr1_1 && key1_1) || (isr2_1 && key2_1)) sx[3] = -1e30f;
                    }
                }
            }

            // exp + pack into P fragments for this group
            float p00 = __expf(s0[0]), p01 = __expf(s0[1]);
            float p02 = __expf(s0[2]), p03 = __expf(s0[3]);
            float p10 = __expf(s1[0]), p11 = __expf(s1[1]);
            float p12 = __expf(s1[2]), p13 = __expf(s1[3]);
            lsum0 += p00 + p01 + p10 + p11;
            lsum1 += p02 + p03 + p12 + p13;
            const unsigned a0 = pack2h(p00, p01);
            const unsigned a1 = pack2h(p02, p03);
            const unsigned a2 = pack2h(p10, p11);
            const unsigned a3 = pack2h(p12, p13);

            // PV k-step np (keys np*16 .. np*16+15) over all 128 dcols
            const unsigned krow_off = (unsigned)(np * 16 * STR) + vrow;
            #pragma unroll
            for (int dp = 0; dp < 8; ++dp) {
                unsigned off = krow_off + (unsigned)(dp * 32);
                unsigned v0, v1, v2, v3;
                LDSM_X4T(v0, v1, v2, v3, sb + offV + off);
                MMA(o[2*dp],   a0, a1, a2, a3, v0, v1);
                MMA(o[2*dp+1], a0, a1, a2, a3, v2, v3);
            }
        }

        __syncthreads();      // buf p readers done; next iter prefetch may overwrite
    }

    // ---- final: reduce l across quad, normalize, store ----
    lsum0 += __shfl_xor_sync(0xffffffffu, lsum0, 1);
    lsum0 += __shfl_xor_sync(0xffffffffu, lsum0, 2);
    lsum1 += __shfl_xor_sync(0xffffffffu, lsum1, 1);
    lsum1 += __shfl_xor_sync(0xffffffffu, lsum1, 2);
    const float inv0 = 1.0f / lsum0;
    const float inv1 = 1.0f / lsum1;

    float* O0 = O + ((size_t)b*S_ + rg0)*D_;
    float* O1 = O + ((size_t)b*S_ + rg1)*D_;
    #pragma unroll
    for (int nt = 0; nt < 16; ++nt) {
        const int col = nt*8 + m_*2;
        float2 w0 = make_float2(o[nt][0]*inv0, o[nt][1]*inv0);
        float2 w1 = make_float2(o[nt][2]*inv1, o[nt][3]*inv1);
        *reinterpret_cast<float2*>(O0 + col) = w0;
        *reinterpret_cast<float2*>(O1 + col) = w1;
    }
}

extern "C" void kernel_launch(void* const* d_in, const int* in_sizes, int n_in,
                              void* d_out, int out_size)
{
    const float* Q = (const float*)d_in[0];
    const float* K = (const float*)d_in[1];
    const float* V = (const float*)d_in[2];
    const unsigned char* kpm = (const unsigned char*)d_in[3];
    const int* cls = (const int*)d_in[4];
    float* O = (float*)d_out;

    // prepass: f32 -> f16 (Q pre-scaled)
    dim3 cgrid((B_*S_*D_/4) / 256, 3);
    cvt_kernel<<<cgrid, 256>>>(Q, K, V);

    cudaFuncSetAttribute(fa_f16_kernel, cudaFuncAttributeMaxDynamicSharedMemorySize, SMEM_BYTES);
    dim3 grid(S_/BQ, B_);
    fa_f16_kernel<<<grid, NT, SMEM_BYTES>>>(kpm, cls, O);
}